// round 3
// baseline (speedup 1.0000x reference)
#include <cuda_runtime.h>
#include <cuda_bf16.h>

#define BB 32
#define TT 36
#define NN 10000
#define FF 3
#define RR 20
#define HH 10
#define CHUNKS 10                           // blocks per batch; 1000 nodes each
#define NODES_PER_CHUNK (NN / CHUNKS)       // 1000
#define ACTIVE_THREADS (NODES_PER_CHUNK/4)  // 250 threads own 4 nodes each
#define GRID_TOTAL (BB * CHUNKS)            // 320 blocks
#define PRED_ELEMS (BB*HH*NN)               // 3,200,000
#define REG_ELEMS  (BB*HH*RR)               // 6,400
#define NAN_CAP    (BB*NN)

// Scratch (device globals — no allocation allowed)
__device__ float g_ps[BB][CHUNKS][RR];      // partial region sums
__device__ float g_pc[BB][CHUNKS][RR];      // partial region counts
__device__ int   g_nan_count = 0;
__device__ int   g_nan_list[NAN_CAP];
__device__ unsigned g_done = 0;

// ---------------------------------------------------------------------------
// Single fused kernel. grid = (CHUNKS, BB), block = 256 (250 active).
// Last-finishing block runs the finalize (deterministic: it reads ALL
// partials in fixed order, so the result is independent of which block it is).
__global__ void __launch_bounds__(256) k_main(const float* __restrict__ seq,
                                              const void* __restrict__ cid_raw,
                                              float* __restrict__ out) {
    const int tid   = threadIdx.x;
    const int lane  = tid & 31;
    const int warp  = tid >> 5;
    const int chunk = blockIdx.x;
    const int b     = blockIdx.y;

    __shared__ int   s_is64;
    __shared__ float s_rs[8][RR];
    __shared__ float s_rc[8][RR];
    __shared__ int   s_last;

    // --- dtype detect (int64 vs int32 cluster_id): warp 0, parallel ---
    if (warp == 0) {
        const int* c32 = (const int*)cid_raw;
        int ok = 1;
        #pragma unroll
        for (int k = 0; k < 4; k++) {
            int idx = (lane * 4 + k) * 2;
            int lo = c32[idx], hi = c32[idx + 1];
            if (hi != 0 || (unsigned)lo >= 64u) ok = 0;
        }
        unsigned bal = __ballot_sync(0xffffffffu, ok);
        if (lane == 0) s_is64 = (bal == 0xffffffffu);
    }

    // --- NaN-aware time mean over T for 4 consecutive nodes ---
    const bool active = (tid < ACTIVE_THREADS);
    const int n0 = chunk * NODES_PER_CHUNK + tid * 4;

    float s0=0.f,s1=0.f,s2=0.f,s3=0.f;
    float c0=0.f,c1=0.f,c2=0.f,c3=0.f;

    if (active) {
        const float* base = seq + ((size_t)b * TT * NN + n0) * FF;
        #pragma unroll 6
        for (int t = 0; t < TT; t++) {
            const float* p = base + (size_t)t * (NN * FF);
            float4 v0 = __ldg((const float4*)(p));
            float4 v1 = __ldg((const float4*)(p + 4));
            float4 v2 = __ldg((const float4*)(p + 8));
            float a0 = v0.x, a1 = v0.w, a2 = v1.z, a3 = v2.y;
            if (a0 == a0) { s0 += a0; c0 += 1.f; }
            if (a1 == a1) { s1 += a1; c1 += 1.f; }
            if (a2 == a2) { s2 += a2; c2 += 1.f; }
            if (a3 == a3) { s3 += a3; c3 += 1.f; }
        }
    }

    float m0 = s0/c0, m1 = s1/c1, m2 = s2/c2, m3 = s3/c3;  // 0/0 -> NaN

    // --- write pred output tiled over H (rare NaNs patched by finalizer) ---
    if (active) {
        float4 r; r.x = m0; r.y = m1; r.z = m2; r.w = m3;
        float* ob = out + (size_t)b * (HH * NN) + n0;
        #pragma unroll
        for (int h = 0; h < HH; h++)
            *(float4*)(ob + h * NN) = r;

        if (c0 == 0.f) { int i = atomicAdd(&g_nan_count, 1); if (i < NAN_CAP) g_nan_list[i] = b * NN + n0;     }
        if (c1 == 0.f) { int i = atomicAdd(&g_nan_count, 1); if (i < NAN_CAP) g_nan_list[i] = b * NN + n0 + 1; }
        if (c2 == 0.f) { int i = atomicAdd(&g_nan_count, 1); if (i < NAN_CAP) g_nan_list[i] = b * NN + n0 + 2; }
        if (c3 == 0.f) { int i = atomicAdd(&g_nan_count, 1); if (i < NAN_CAP) g_nan_list[i] = b * NN + n0 + 3; }
    }

    __syncthreads();   // s_is64 ready

    // --- cluster ids for the 4 nodes ---
    int r0=-1, r1=-1, r2=-1, r3=-1;
    if (active) {
        if (s_is64) {
            const long long* c64 = (const long long*)cid_raw;
            r0=(int)c64[n0]; r1=(int)c64[n0+1]; r2=(int)c64[n0+2]; r3=(int)c64[n0+3];
        } else {
            const int* c32 = (const int*)cid_raw;
            int4 cv = __ldg((const int4*)(c32 + n0));
            r0=cv.x; r1=cv.y; r2=cv.z; r3=cv.w;
        }
    }
    float v0 = (c0>0.f)?m0:0.f, v1 = (c1>0.f)?m1:0.f;
    float v2 = (c2>0.f)?m2:0.f, v3 = (c3>0.f)?m3:0.f;
    float k0 = (c0>0.f)?1.f:0.f, k1 = (c1>0.f)?1.f:0.f;
    float k2 = (c2>0.f)?1.f:0.f, k3 = (c3>0.f)?1.f:0.f;

    // --- per-warp region reduction (deterministic shuffles) ---
    #pragma unroll
    for (int r = 0; r < RR; r++) {
        float s = 0.f, c = 0.f;
        if (r0 == r) { s += v0; c += k0; }
        if (r1 == r) { s += v1; c += k1; }
        if (r2 == r) { s += v2; c += k2; }
        if (r3 == r) { s += v3; c += k3; }
        #pragma unroll
        for (int o = 16; o > 0; o >>= 1) {
            s += __shfl_xor_sync(0xffffffffu, s, o);
            c += __shfl_xor_sync(0xffffffffu, c, o);
        }
        if (lane == 0) { s_rs[warp][r] = s; s_rc[warp][r] = c; }
    }
    __syncthreads();

    // --- cross-warp reduce + global partial write ---
    if (tid < RR) {
        float s = 0.f, c = 0.f;
        #pragma unroll
        for (int w = 0; w < 8; w++) { s += s_rs[w][tid]; c += s_rc[w][tid]; }
        g_ps[b][chunk][tid] = s;
        g_pc[b][chunk][tid] = c;
    }

    // =======================================================================
    // Last-block-finalizes: release partials, elect the last block.
    __threadfence();
    __syncthreads();
    if (tid == 0) {
        unsigned v = atomicAdd(&g_done, 1u);
        s_last = (v == GRID_TOTAL - 1u);
    }
    __syncthreads();
    if (!s_last) return;
    __threadfence();   // acquire: all other blocks' partials now visible

    // ---------------- finalize (one block, 256 threads) ----------------
    __shared__ float s_rsum[BB*RR];
    __shared__ float s_rcnt[BB*RR];
    __shared__ float sh0[256], sh1[256], sh2[256], sh3[256];
    const int t = tid;

    for (int i = t; i < BB*RR; i += 256) {
        int bb = i / RR, rr = i % RR;
        float s = 0.f, c = 0.f;
        #pragma unroll
        for (int ch = 0; ch < CHUNKS; ch++) { s += g_ps[bb][ch][rr]; c += g_pc[bb][ch][rr]; }
        s_rsum[i] = s; s_rcnt[i] = c;
    }
    __syncthreads();

    // g1 = total_sum/total_cnt (regions partition nodes; H-tiling cancels);
    // g2 = mean of valid region-means
    float ts=0.f, tc=0.f, ms=0.f, mc=0.f;
    for (int i = t; i < BB*RR; i += 256) {
        float s = s_rsum[i], c = s_rcnt[i];
        ts += s; tc += c;
        if (c > 0.f) { ms += s / c; mc += 1.f; }
    }
    sh0[t]=ts; sh1[t]=tc; sh2[t]=ms; sh3[t]=mc;
    __syncthreads();
    #pragma unroll
    for (int o = 128; o > 0; o >>= 1) {
        if (t < o) { sh0[t]+=sh0[t+o]; sh1[t]+=sh1[t+o]; sh2[t]+=sh2[t+o]; sh3[t]+=sh3[t+o]; }
        __syncthreads();
    }
    const float g1 = sh0[0] / sh1[0];
    const float g2 = sh2[0] / sh3[0];

    // regional output [B, H, R] (independent of h)
    for (int i = t; i < REG_ELEMS; i += 256) {
        int bb = i / (HH * RR);
        int rr = i % RR;
        float c = s_rcnt[bb * RR + rr];
        out[PRED_ELEMS + i] = (c > 0.f) ? (s_rsum[bb * RR + rr] / c) : g2;
    }

    // NaN fixup in pred output (expected 0 entries; order-independent writes)
    int cnt = g_nan_count;
    if (cnt > NAN_CAP) cnt = NAN_CAP;
    for (int i = t; i < cnt; i += 256) {
        int code = g_nan_list[i];
        int bb = code / NN, n = code % NN;
        float* ob = out + (size_t)bb * (HH * NN) + n;
        #pragma unroll
        for (int h = 0; h < HH; h++) ob[h * NN] = g1;
    }
    __syncthreads();
    if (t == 0) { g_nan_count = 0; g_done = 0; }   // reset for graph replay
}

// ---------------------------------------------------------------------------
extern "C" void kernel_launch(void* const* d_in, const int* in_sizes, int n_in,
                              void* d_out, int out_size) {
    const float* seq = (const float*)d_in[0];
    const void*  cid = d_in[1];
    float* out = (float*)d_out;

    dim3 grid(CHUNKS, BB);
    k_main<<<grid, 256>>>(seq, cid, out);
}